// round 6
// baseline (speedup 1.0000x reference)
#include <cuda_runtime.h>

// Normalized correlation layer, GB300 sm_103a — round 6.
// Identity: sum((a-ma)(b-mb))/(sa*sb) = (S_ab - 25*ma*mb) * (1/sa)*(1/sb).
//
// Round-6 changes vs round 5 (same w-paired FMA2 + coalesced staged stores):
//  - sd[d]==d made COMPILE-TIME via template: FAST kernel covers r<=34
//    (round 5 had ~90 runtime branch regions per phase from the row2 clamp
//    -> BSSY/BSYNC overhead + broken load batching). EDGE kernel (r=35,36)
//    keeps the runtime clamp; it's 64/1184 CTAs, hidden in the tail.
//  - image1 window cached in registers a1r[5][5], loaded once per phase:
//    inner loop per rho = 15 batchable LDS + 150 FMA2 (was 40 LDS + branches).

#define NB 16
#define NR 37

typedef unsigned long long u64;

__device__ __forceinline__ u64 fma2_(u64 a, u64 b, u64 c) {
    u64 d; asm("fma.rn.f32x2 %0, %1, %2, %3;" : "=l"(d) : "l"(a), "l"(b), "l"(c)); return d;
}
__device__ __forceinline__ u64 mul2_(u64 a, u64 b) {
    u64 d; asm("mul.rn.f32x2 %0, %1, %2;" : "=l"(d) : "l"(a), "l"(b)); return d;
}
__device__ __forceinline__ u64 add2_(u64 a, u64 b) {
    u64 d; asm("add.rn.f32x2 %0, %1, %2;" : "=l"(d) : "l"(a), "l"(b)); return d;
}
__device__ __forceinline__ u64 pk2(float x, float y) {
    u64 r; asm("mov.b64 %0, {%1, %2};" : "=l"(r) : "f"(x), "f"(y)); return r;
}
__device__ __forceinline__ float2 upk2(u64 v) {
    float2 f; asm("mov.b64 {%0, %1}, %2;" : "=f"(f.x), "=f"(f.y) : "l"(v)); return f;
}

// Stats. g_nA = -25*mean1, layout [b][37][j][c].  g_rA = rstd1, same.
// Image2 stats transposed & j-pair-packed: float2 t = (stat[2t], stat[2t+1]),
// layout [b][39][c][t] -> corr kernel loads a w-pair with one LDG.64.
__device__ float  g_nA [NB * NR * 12 * 128];
__device__ float  g_rA [NB * NR * 12 * 128];
__device__ float2 g_mBt[NB * 39 * 128 * 6];
__device__ float2 g_rBt[NB * 39 * 128 * 6];

// ---------------------------------------------------------------------------
// Pass 1: per-patch per-channel mean and rstd.
// grid.x: 0..36 -> image1 row start; 37..75 -> image2 row start (x-37).
// ---------------------------------------------------------------------------
__global__ __launch_bounds__(384) void nc_stats_kernel(
    const float* __restrict__ in1, const float* __restrict__ in2)
{
    __shared__ u64 slab[5 * 16 * 64];
    const int bx  = blockIdx.x;
    const int b   = blockIdx.y;
    const int tid = threadIdx.x;

    const bool img1 = bx < NR;
    const int  st   = img1 ? bx : bx - NR;
    const int  roff = img1 ? 2 : 4;
    const u64* inv  = (const u64*)(img1 ? in1 : in2);

    for (int i = tid; i < 5 * 16 * 64; i += 384) {
        int c = i & 63, col = (i >> 6) & 15, dr = i >> 10;
        int row = st + dr - roff;
        int cg  = col - 2;
        u64 v = 0ull;
        if ((unsigned)row < 37u && (unsigned)cg < 12u)
            v = inv[((b * 37 + row) * 12 + cg) * 64 + c];
        slab[i] = v;
    }
    __syncthreads();

    for (int t = tid; t < 12 * 64; t += 384) {
        int j = t >> 6, c = t & 63;   // c = channel pair (2c, 2c+1)
        u64 s = 0ull, q = 0ull;
        #pragma unroll
        for (int dr = 0; dr < 5; dr++) {
            #pragma unroll
            for (int dc = 0; dc < 5; dc++) {
                u64 v = slab[(dr * 16 + j + dc) * 64 + c];
                s = add2_(s, v);
                q = fma2_(v, v, q);
            }
        }
        float2 sf = upk2(s), qf = upk2(q);
        float mx = sf.x * 0.04f, my = sf.y * 0.04f;
        float vx = qf.x * 0.04f - mx * mx;
        float vy = qf.y * 0.04f - my * my;
        float rx = rsqrtf(vx), ry = rsqrtf(vy);

        if (img1) {
            int idx = ((b * 37 + st) * 12 + j) * 128 + 2 * c;
            g_nA[idx]     = -25.0f * mx;
            g_nA[idx + 1] = -25.0f * my;
            g_rA[idx]     = rx;
            g_rA[idx + 1] = ry;
        } else {
            float* mB = (float*)g_mBt;
            float* rB = (float*)g_rBt;
            int base = ((b * 39 + st) * 128 + 2 * c) * 12 + j;
            mB[base]      = mx;
            mB[base + 12] = my;
            rB[base]      = rx;
            rB[base + 12] = ry;
        }
    }
}

// ---------------------------------------------------------------------------
// Pass 2: correlation. CTA per (r, b, c-half). 384 threads = 64 c x 6 jj.
// Two j-phases (j = jj and jj+6) share the slabs.
// ---------------------------------------------------------------------------
#define PB_OFF   0                    // u64[9][15][64]  = 8640
#define A1_OFF   8640                 // u64[5][16][64]  = 5120
#define SMEM_U64 13760                // 110080 bytes
#define STAGE_F  (SMEM_U64 * 2)       // float offset of stage
#define STAGE_ROW 3848                // floats per j-tile (3840 + 8 pad)
#define SMEM_BYTES (SMEM_U64 * 8 + 6 * STAGE_ROW * 4)   // 202432

template <bool EDGE>
__global__ __launch_bounds__(384, 1) void nc_corr_kernel(
    const float* __restrict__ in1, const float* __restrict__ in2,
    float* __restrict__ out)
{
    extern __shared__ u64 sm[];
    float* stage = ((float*)sm) + STAGE_F;

    const int r   = EDGE ? (35 + blockIdx.x) : blockIdx.x;
    const int b   = blockIdx.y;
    const int chv = blockIdx.z;        // c-half: 0 or 1
    const int tid = threadIdx.x;
    const int c   = tid & 63;          // channel within half
    const int jj  = tid >> 6;          // 0..5
    const int ch  = chv * 64 + c;      // global channel

    // PB[row][x][c] = (A2[padcol x], A2[padcol x+1]) for pad2 row r+row.
    for (int i = tid; i < 9 * 15 * 64; i += 384) {
        int cc = i & 63, x = (i >> 6) % 15, row = i / (15 * 64);
        int irow = r + row - 4;
        float vlo = 0.f, vhi = 0.f;
        if ((unsigned)irow < 37u) {
            const float* base = in2 + ((b * 37 + irow) * 12) * 128 + chv * 64 + cc;
            int collo = x - 2, colhi = x - 1;
            if ((unsigned)collo < 12u) vlo = base[collo * 128];
            if ((unsigned)colhi < 12u) vhi = base[colhi * 128];
        }
        sm[PB_OFF + i] = pk2(vlo, vhi);
    }
    // A1B[dr][col][c] = broadcast-packed image1 value, pad1 row r+dr.
    for (int i = tid; i < 5 * 16 * 64; i += 384) {
        int cc = i & 63, col = (i >> 6) & 15, dr = i / (16 * 64);
        int irow = r + dr - 2, icol = col - 2;
        float v = 0.f;
        if ((unsigned)irow < 37u && (unsigned)icol < 12u)
            v = in1[((b * 37 + irow) * 12 + icol) * 128 + chv * 64 + cc];
        sm[A1_OFF + i] = pk2(v, v);
    }
    __syncthreads();

    // Patch2 row-start offset for shift d.  FAST: sd == d (compile-time).
    int sd[5];
    #pragma unroll
    for (int d = 0; d < 5; d++) sd[d] = EDGE ? ((r + d <= 38) ? d : d - 2) : d;

    const u64* mBv = (const u64*)g_mBt;
    const u64* rBv = (const u64*)g_rBt;

    #pragma unroll 1
    for (int ph = 0; ph < 2; ph++) {
        const int j = jj + 6 * ph;

        // Image1 window cached in registers: loaded ONCE per phase,
        // reused across all 9 rho iterations (was reloaded per (d,dr)).
        u64 a1r[5][5];
        #pragma unroll
        for (int dr = 0; dr < 5; dr++) {
            const u64* a1row = sm + A1_OFF + dr * (16 * 64) + (j << 6) + c;
            #pragma unroll
            for (int dc = 0; dc < 5; dc++) a1r[dr][dc] = a1row[dc << 6];
        }

        u64 acc[5][6];
        #pragma unroll
        for (int d = 0; d < 5; d++)
            #pragma unroll
            for (int t = 0; t < 6; t++) acc[d][t] = 0ull;

        // Slab-row loop: PB row rho serves every (d, dr) with sd[d]+dr == rho.
        // FAST: dr = rho - d, all bounds static -> straight-line code.
        #pragma unroll 1
        for (int rho = 0; rho < 9; rho++) {
            u64 pb[15];
            const u64* pbrow = sm + PB_OFF + rho * (15 * 64) + c;
            #pragma unroll
            for (int x = 0; x < 15; x++) pb[x] = pbrow[x << 6];

            if (!EDGE) {
                #pragma unroll
                for (int d = 0; d < 5; d++) {
                    const int dr = rho - d;            // compile-time per (rho,d)
                    if (dr >= 0 && dr < 5) {
                        #pragma unroll
                        for (int dc = 0; dc < 5; dc++) {
                            const u64 a = a1r[dr][dc];
                            #pragma unroll
                            for (int t = 0; t < 6; t++)
                                acc[d][t] = fma2_(a, pb[2 * t + dc], acc[d][t]);
                        }
                    }
                }
            } else {
                #pragma unroll
                for (int d = 0; d < 5; d++) {
                    const int dr = rho - sd[d];
                    if ((unsigned)dr < 5u) {
                        #pragma unroll
                        for (int dc = 0; dc < 5; dc++) {
                            u64 a = 0ull;
                            #pragma unroll
                            for (int q = 0; q < 5; q++) if (q == dr) {
                                #pragma unroll
                                for (int s2 = 0; s2 < 5; s2++) if (s2 == dc) a = a1r[q][s2];
                            }
                            #pragma unroll
                            for (int t = 0; t < 6; t++)
                                acc[d][t] = fma2_(a, pb[2 * t + dc], acc[d][t]);
                        }
                    }
                }
            }
        }

        // Epilogue: (S - 25*ma*mb) * ra * rb, w-pair packed; stage in gmem order.
        const int giA = ((b * 37 + r) * 12 + j) * 128 + ch;
        const float na = g_nA[giA];   // -25*mean1
        const float ra = g_rA[giA];
        const u64 na2 = pk2(na, na);
        const u64 ra2 = pk2(ra, ra);
        float* srow = stage + jj * STAGE_ROW + c * 60;

        #pragma unroll
        for (int d = 0; d < 5; d++) {
            const int gb = ((b * 39 + (r + sd[d])) * 128 + ch) * 6;
            #pragma unroll
            for (int t = 0; t < 6; t++) {
                u64 mbp = mBv[gb + t];
                u64 rbp = rBv[gb + t];
                u64 res = mul2_(fma2_(na2, mbp, acc[d][t]), mul2_(ra2, rbp));
                *(u64*)(srow + 12 * d + 2 * t) = res;
            }
        }
        __syncthreads();

        // Flush: 6 j-tiles, each 64c*60w = 3840 contiguous floats in gmem.
        for (int it = 0; it < 15; it++) {
            int f  = it * 384 + tid;
            int jl = f / 960;
            int e  = (f - jl * 960) * 4;
            float4 v = *(float4*)(stage + jl * STAGE_ROW + e);
            int jg = jl + 6 * ph;
            *(float4*)(out + ((b * 37 + r) * 12 + jg) * 7680 + chv * 3840 + e) = v;
        }
        __syncthreads();
    }
}

// ---------------------------------------------------------------------------
extern "C" void kernel_launch(void* const* d_in, const int* in_sizes, int n_in,
                              void* d_out, int out_size)
{
    const float* in1 = (const float*)d_in[0];
    const float* in2 = (const float*)d_in[1];
    float* out = (float*)d_out;

    cudaFuncSetAttribute(nc_corr_kernel<false>,
                         cudaFuncAttributeMaxDynamicSharedMemorySize, SMEM_BYTES);
    cudaFuncSetAttribute(nc_corr_kernel<true>,
                         cudaFuncAttributeMaxDynamicSharedMemorySize, SMEM_BYTES);

    nc_stats_kernel<<<dim3(NR + 39, NB), 384>>>(in1, in2);
    nc_corr_kernel<false><<<dim3(35, NB, 2), 384, SMEM_BYTES>>>(in1, in2, out);
    nc_corr_kernel<true ><<<dim3(2,  NB, 2), 384, SMEM_BYTES>>>(in1, in2, out);
}

// round 7
// speedup vs baseline: 1.6448x; 1.6448x over previous
#include <cuda_runtime.h>

// Normalized correlation layer, GB300 sm_103a — round 7.
// Identity: sum((a-ma)(b-mb))/(sa*sb) = (S_ab - 25*ma*mb) * (1/sa)*(1/sb).
//
// Round-7 changes vs rounds 5/6:
//  - t-half split: acc[5][3] (30 regs) + pb[9] (18) + a1r[5][5] (50) ~= 130
//    total regs -> no spills (round 6 spilled at ~160+).
//  - rho loop FULLY UNROLLED -> dr = rho-d compile-time, zero branches,
//    batched 9-wide LDS per rho (round 5 had ~90 runtime branch regions).
//  - single corr launch; r=35,36 take an internal runtime-sd EDGE path.
//  - image2 stats laid out [b][39][t][ch] -> epilogue LDG.64 lane-contiguous.

#define NB 16
#define NR 37

typedef unsigned long long u64;

__device__ __forceinline__ u64 fma2_(u64 a, u64 b, u64 c) {
    u64 d; asm("fma.rn.f32x2 %0, %1, %2, %3;" : "=l"(d) : "l"(a), "l"(b), "l"(c)); return d;
}
__device__ __forceinline__ u64 mul2_(u64 a, u64 b) {
    u64 d; asm("mul.rn.f32x2 %0, %1, %2;" : "=l"(d) : "l"(a), "l"(b)); return d;
}
__device__ __forceinline__ u64 add2_(u64 a, u64 b) {
    u64 d; asm("add.rn.f32x2 %0, %1, %2;" : "=l"(d) : "l"(a), "l"(b)); return d;
}
__device__ __forceinline__ u64 pk2(float x, float y) {
    u64 r; asm("mov.b64 %0, {%1, %2};" : "=l"(r) : "f"(x), "f"(y)); return r;
}
__device__ __forceinline__ float2 upk2(u64 v) {
    float2 f; asm("mov.b64 {%0, %1}, %2;" : "=f"(f.x), "=f"(f.y) : "l"(v)); return f;
}

// Stats. g_nA = -25*mean1, g_rA = rstd1, layout [b][37][j][ch].
// Image2 stats w-pair packed, layout u64[b][39][t][ch] where the u64 at
// (row-start, t, ch) = (stat[j2=2t], stat[j2=2t+1]) -> epilogue LDG.64 is
// lane-contiguous in ch.
__device__ float  g_nA [NB * NR * 12 * 128];
__device__ float  g_rA [NB * NR * 12 * 128];
__device__ float2 g_mBt[NB * 39 * 6 * 128];
__device__ float2 g_rBt[NB * 39 * 6 * 128];

// ---------------------------------------------------------------------------
// Pass 1: per-patch per-channel mean and rstd.
// grid.x: 0..36 -> image1 row start; 37..75 -> image2 row start (x-37).
// ---------------------------------------------------------------------------
__global__ __launch_bounds__(384) void nc_stats_kernel(
    const float* __restrict__ in1, const float* __restrict__ in2)
{
    __shared__ u64 slab[5 * 16 * 64];
    const int bx  = blockIdx.x;
    const int b   = blockIdx.y;
    const int tid = threadIdx.x;

    const bool img1 = bx < NR;
    const int  st   = img1 ? bx : bx - NR;
    const int  roff = img1 ? 2 : 4;
    const u64* inv  = (const u64*)(img1 ? in1 : in2);

    for (int i = tid; i < 5 * 16 * 64; i += 384) {
        int c = i & 63, col = (i >> 6) & 15, dr = i >> 10;
        int row = st + dr - roff;
        int cg  = col - 2;
        u64 v = 0ull;
        if ((unsigned)row < 37u && (unsigned)cg < 12u)
            v = inv[((b * 37 + row) * 12 + cg) * 64 + c];
        slab[i] = v;
    }
    __syncthreads();

    for (int t = tid; t < 12 * 64; t += 384) {
        int j = t >> 6, c = t & 63;   // c = channel pair (2c, 2c+1)
        u64 s = 0ull, q = 0ull;
        #pragma unroll
        for (int dr = 0; dr < 5; dr++) {
            #pragma unroll
            for (int dc = 0; dc < 5; dc++) {
                u64 v = slab[(dr * 16 + j + dc) * 64 + c];
                s = add2_(s, v);
                q = fma2_(v, v, q);
            }
        }
        float2 sf = upk2(s), qf = upk2(q);
        float mx = sf.x * 0.04f, my = sf.y * 0.04f;
        float vx = qf.x * 0.04f - mx * mx;
        float vy = qf.y * 0.04f - my * my;
        float rx = rsqrtf(vx), ry = rsqrtf(vy);

        if (img1) {
            int idx = ((b * 37 + st) * 12 + j) * 128 + 2 * c;
            g_nA[idx]     = -25.0f * mx;
            g_nA[idx + 1] = -25.0f * my;
            g_rA[idx]     = rx;
            g_rA[idx + 1] = ry;
        } else {
            // float view of u64[b][39][t][ch]: fidx = (((b*39+st)*6+t)*128+ch)*2 + (j&1)
            float* mB = (float*)g_mBt;
            float* rB = (float*)g_rBt;
            int base = (((b * 39 + st) * 6 + (j >> 1)) * 128) * 2 + (j & 1);
            mB[base + 4 * c]     = mx;   // ch = 2c
            mB[base + 4 * c + 2] = my;   // ch = 2c+1
            rB[base + 4 * c]     = rx;
            rB[base + 4 * c + 2] = ry;
        }
    }
}

// ---------------------------------------------------------------------------
// Pass 2: correlation. CTA per (r, b, c-half). 384 threads = 64 c x 6 jj.
// Two j-phases (j = jj and jj+6) share the slabs. Within a phase, two
// t-halves (w-pairs 0..2 and 3..5) keep the register live-set small.
// ---------------------------------------------------------------------------
#define PB_OFF   0                    // u64[9][15][64]  = 8640
#define A1_OFF   8640                 // u64[5][16][64]  = 5120
#define SMEM_U64 13760                // 110080 bytes
#define STAGE_F  (SMEM_U64 * 2)       // float offset of stage
#define STAGE_ROW 3848                // floats per j-tile (3840 + 8 pad)
#define SMEM_BYTES (SMEM_U64 * 8 + 6 * STAGE_ROW * 4)   // 202432

__global__ __launch_bounds__(384, 1) void nc_corr_kernel(
    const float* __restrict__ in1, const float* __restrict__ in2,
    float* __restrict__ out)
{
    extern __shared__ u64 sm[];
    float* stage = ((float*)sm) + STAGE_F;

    const int r   = blockIdx.x;
    const int b   = blockIdx.y;
    const int chv = blockIdx.z;        // c-half: 0 or 1
    const int tid = threadIdx.x;
    const int c   = tid & 63;          // channel within half
    const int jj  = tid >> 6;          // 0..5
    const int ch  = chv * 64 + c;      // global channel

    // PB[row][x][c] = (A2[padcol x], A2[padcol x+1]) for pad2 row r+row.
    for (int i = tid; i < 9 * 15 * 64; i += 384) {
        int cc = i & 63, x = (i >> 6) % 15, row = i / (15 * 64);
        int irow = r + row - 4;
        float vlo = 0.f, vhi = 0.f;
        if ((unsigned)irow < 37u) {
            const float* base = in2 + ((b * 37 + irow) * 12) * 128 + chv * 64 + cc;
            int collo = x - 2, colhi = x - 1;
            if ((unsigned)collo < 12u) vlo = base[collo * 128];
            if ((unsigned)colhi < 12u) vhi = base[colhi * 128];
        }
        sm[PB_OFF + i] = pk2(vlo, vhi);
    }
    // A1B[dr][col][c] = broadcast-packed image1 value, pad1 row r+dr.
    for (int i = tid; i < 5 * 16 * 64; i += 384) {
        int cc = i & 63, col = (i >> 6) & 15, dr = i / (16 * 64);
        int irow = r + dr - 2, icol = col - 2;
        float v = 0.f;
        if ((unsigned)irow < 37u && (unsigned)icol < 12u)
            v = in1[((b * 37 + irow) * 12 + icol) * 128 + chv * 64 + cc];
        sm[A1_OFF + i] = pk2(v, v);
    }
    __syncthreads();

    const u64* mBv = (const u64*)g_mBt;
    const u64* rBv = (const u64*)g_rBt;
    const bool fast = (r <= 34);       // sd[d] == d  (no row2 clamp)

    #pragma unroll 1
    for (int ph = 0; ph < 2; ph++) {
        const int j = jj + 6 * ph;

        const int giA = ((b * 37 + r) * 12 + j) * 128 + ch;
        const float na = g_nA[giA];    // -25*mean1
        const float ra = g_rA[giA];
        const u64 na2 = pk2(na, na);
        const u64 ra2 = pk2(ra, ra);
        float* srow = stage + jj * STAGE_ROW + c * 60;

        if (fast) {
            // Image1 window in registers, reused across both halves & all rho.
            u64 a1r[5][5];
            #pragma unroll
            for (int dr = 0; dr < 5; dr++) {
                const u64* a1row = sm + A1_OFF + dr * (16 * 64) + (j << 6) + c;
                #pragma unroll
                for (int dc = 0; dc < 5; dc++) a1r[dr][dc] = a1row[dc << 6];
            }

            #pragma unroll 1
            for (int th = 0; th < 2; th++) {
                u64 acc[5][3];
                #pragma unroll
                for (int d = 0; d < 5; d++)
                    #pragma unroll
                    for (int t = 0; t < 3; t++) acc[d][t] = 0ull;

                const u64* pbbase = sm + PB_OFF + ((th * 6) << 6) + c;

                // Fully unrolled: dr = rho - d is compile-time -> no branches,
                // 9 batchable LDS per rho feeding ~42 FMA2.
                #pragma unroll
                for (int rho = 0; rho < 9; rho++) {
                    u64 pb[9];
                    #pragma unroll
                    for (int x = 0; x < 9; x++)
                        pb[x] = pbbase[rho * (15 * 64) + (x << 6)];
                    #pragma unroll
                    for (int d = 0; d < 5; d++) {
                        const int dr = rho - d;
                        if (dr >= 0 && dr < 5) {
                            #pragma unroll
                            for (int dc = 0; dc < 5; dc++) {
                                const u64 a = a1r[dr][dc];
                                #pragma unroll
                                for (int t = 0; t < 3; t++)
                                    acc[d][t] = fma2_(a, pb[2 * t + dc], acc[d][t]);
                            }
                        }
                    }
                }

                // Epilogue for this half: (S - 25 ma mb) * ra * rb.
                #pragma unroll
                for (int d = 0; d < 5; d++) {
                    const int gbase = ((b * 39 + (r + d)) * 6 + th * 3) * 128 + ch;
                    #pragma unroll
                    for (int t = 0; t < 3; t++) {
                        u64 mbp = mBv[gbase + t * 128];
                        u64 rbp = rBv[gbase + t * 128];
                        u64 res = mul2_(fma2_(na2, mbp, acc[d][t]), mul2_(ra2, rbp));
                        *(u64*)(srow + 12 * d + 2 * (th * 3 + t)) = res;
                    }
                }
            }
        } else {
            // EDGE path (r = 35, 36): runtime sd from the row2 clamp.
            int sd[5];
            #pragma unroll
            for (int d = 0; d < 5; d++) sd[d] = (r + d <= 38) ? d : d - 2;

            #pragma unroll 1
            for (int th = 0; th < 2; th++) {
                u64 acc[5][3];
                #pragma unroll
                for (int d = 0; d < 5; d++)
                    #pragma unroll
                    for (int t = 0; t < 3; t++) acc[d][t] = 0ull;

                const u64* pbbase = sm + PB_OFF + ((th * 6) << 6) + c;

                #pragma unroll 1
                for (int rho = 0; rho < 9; rho++) {
                    u64 pb[9];
                    #pragma unroll
                    for (int x = 0; x < 9; x++)
                        pb[x] = pbbase[rho * (15 * 64) + (x << 6)];
                    #pragma unroll
                    for (int d = 0; d < 5; d++) {
                        const int dr = rho - sd[d];
                        if ((unsigned)dr < 5u) {
                            const u64* a1row = sm + A1_OFF + dr * (16 * 64) + (j << 6) + c;
                            #pragma unroll
                            for (int dc = 0; dc < 5; dc++) {
                                const u64 a = a1row[dc << 6];
                                #pragma unroll
                                for (int t = 0; t < 3; t++)
                                    acc[d][t] = fma2_(a, pb[2 * t + dc], acc[d][t]);
                            }
                        }
                    }
                }

                #pragma unroll
                for (int d = 0; d < 5; d++) {
                    const int gbase = ((b * 39 + (r + sd[d])) * 6 + th * 3) * 128 + ch;
                    #pragma unroll
                    for (int t = 0; t < 3; t++) {
                        u64 mbp = mBv[gbase + t * 128];
                        u64 rbp = rBv[gbase + t * 128];
                        u64 res = mul2_(fma2_(na2, mbp, acc[d][t]), mul2_(ra2, rbp));
                        *(u64*)(srow + 12 * d + 2 * (th * 3 + t)) = res;
                    }
                }
            }
        }
        __syncthreads();

        // Flush: 6 j-tiles, each 64c*60w = 3840 contiguous floats in gmem.
        for (int it = 0; it < 15; it++) {
            int f  = it * 384 + tid;
            int jl = f / 960;
            int e  = (f - jl * 960) * 4;
            float4 v = *(float4*)(stage + jl * STAGE_ROW + e);
            int jg = jl + 6 * ph;
            *(float4*)(out + ((b * 37 + r) * 12 + jg) * 7680 + chv * 3840 + e) = v;
        }
        __syncthreads();
    }
}

// ---------------------------------------------------------------------------
extern "C" void kernel_launch(void* const* d_in, const int* in_sizes, int n_in,
                              void* d_out, int out_size)
{
    const float* in1 = (const float*)d_in[0];
    const float* in2 = (const float*)d_in[1];
    float* out = (float*)d_out;

    cudaFuncSetAttribute(nc_corr_kernel,
                         cudaFuncAttributeMaxDynamicSharedMemorySize, SMEM_BYTES);

    nc_stats_kernel<<<dim3(NR + 39, NB), 384>>>(in1, in2);
    nc_corr_kernel<<<dim3(NR, NB, 2), 384, SMEM_BYTES>>>(in1, in2, out);
}

// round 8
// speedup vs baseline: 2.0465x; 1.2442x over previous
#include <cuda_runtime.h>

// Normalized correlation layer, GB300 sm_103a — round 8.
// Identity: sum((a-ma)(b-mb))/(sa*sb) = (S_ab - 25*ma*mb) * (1/sa)*(1/sb).
//
// Round-8: one 768-thread CTA per (r,b,c-half): 64 c x 6 jj x 2 t-halves.
//  - t-half split moved into THREADS -> per-thread regs: acc[5][3]=30 +
//    pb[9]=18 + a1f 25 f32 ~= 73, fits the 85-reg cap (768 thr) w/o spills,
//    while keeping 24 warps/SM (rounds at 12 warps all idled ~76%).
//  - a1 cached as f32 scalars; one mov.b64{v,v} dup feeds 3 FMA2.
//  - row2 edge clamp (r=35,36) == output duplication: handled by TWO
//    predicated acc selects in the epilogue. No edge path, no branches,
//    rho loop fully unrolled/static.
//  - staged coalesced flush kept (92KB stage; 182KB smem, 1 CTA/SM).

#define NB 16
#define NR 37

typedef unsigned long long u64;

__device__ __forceinline__ u64 fma2_(u64 a, u64 b, u64 c) {
    u64 d; asm("fma.rn.f32x2 %0, %1, %2, %3;" : "=l"(d) : "l"(a), "l"(b), "l"(c)); return d;
}
__device__ __forceinline__ u64 mul2_(u64 a, u64 b) {
    u64 d; asm("mul.rn.f32x2 %0, %1, %2;" : "=l"(d) : "l"(a), "l"(b)); return d;
}
__device__ __forceinline__ u64 add2_(u64 a, u64 b) {
    u64 d; asm("add.rn.f32x2 %0, %1, %2;" : "=l"(d) : "l"(a), "l"(b)); return d;
}
__device__ __forceinline__ u64 pk2(float x, float y) {
    u64 r; asm("mov.b64 %0, {%1, %2};" : "=l"(r) : "f"(x), "f"(y)); return r;
}
__device__ __forceinline__ float2 upk2(u64 v) {
    float2 f; asm("mov.b64 {%0, %1}, %2;" : "=f"(f.x), "=f"(f.y) : "l"(v)); return f;
}

// Stats. g_nA = -25*mean1, g_rA = rstd1, layout [b][37][j][ch].
// Image2 stats w-pair packed, u64[b][39][t][ch]: the u64 at (row-start,t,ch)
// = (stat[j2=2t], stat[j2=2t+1]) -> epilogue LDG.64 lane-contiguous in ch.
__device__ float  g_nA [NB * NR * 12 * 128];
__device__ float  g_rA [NB * NR * 12 * 128];
__device__ float2 g_mBt[NB * 39 * 6 * 128];
__device__ float2 g_rBt[NB * 39 * 6 * 128];

// ---------------------------------------------------------------------------
// Pass 1: per-patch per-channel mean and rstd (unchanged from round 7).
// grid.x: 0..36 -> image1 row start; 37..75 -> image2 row start (x-37).
// ---------------------------------------------------------------------------
__global__ __launch_bounds__(384) void nc_stats_kernel(
    const float* __restrict__ in1, const float* __restrict__ in2)
{
    __shared__ u64 slab[5 * 16 * 64];
    const int bx  = blockIdx.x;
    const int b   = blockIdx.y;
    const int tid = threadIdx.x;

    const bool img1 = bx < NR;
    const int  st   = img1 ? bx : bx - NR;
    const int  roff = img1 ? 2 : 4;
    const u64* inv  = (const u64*)(img1 ? in1 : in2);

    for (int i = tid; i < 5 * 16 * 64; i += 384) {
        int c = i & 63, col = (i >> 6) & 15, dr = i >> 10;
        int row = st + dr - roff;
        int cg  = col - 2;
        u64 v = 0ull;
        if ((unsigned)row < 37u && (unsigned)cg < 12u)
            v = inv[((b * 37 + row) * 12 + cg) * 64 + c];
        slab[i] = v;
    }
    __syncthreads();

    for (int t = tid; t < 12 * 64; t += 384) {
        int j = t >> 6, c = t & 63;   // c = channel pair (2c, 2c+1)
        u64 s = 0ull, q = 0ull;
        #pragma unroll
        for (int dr = 0; dr < 5; dr++) {
            #pragma unroll
            for (int dc = 0; dc < 5; dc++) {
                u64 v = slab[(dr * 16 + j + dc) * 64 + c];
                s = add2_(s, v);
                q = fma2_(v, v, q);
            }
        }
        float2 sf = upk2(s), qf = upk2(q);
        float mx = sf.x * 0.04f, my = sf.y * 0.04f;
        float vx = qf.x * 0.04f - mx * mx;
        float vy = qf.y * 0.04f - my * my;
        float rx = rsqrtf(vx), ry = rsqrtf(vy);

        if (img1) {
            int idx = ((b * 37 + st) * 12 + j) * 128 + 2 * c;
            g_nA[idx]     = -25.0f * mx;
            g_nA[idx + 1] = -25.0f * my;
            g_rA[idx]     = rx;
            g_rA[idx + 1] = ry;
        } else {
            float* mB = (float*)g_mBt;
            float* rB = (float*)g_rBt;
            int base = (((b * 39 + st) * 6 + (j >> 1)) * 128) * 2 + (j & 1);
            mB[base + 4 * c]     = mx;   // ch = 2c
            mB[base + 4 * c + 2] = my;   // ch = 2c+1
            rB[base + 4 * c]     = rx;
            rB[base + 4 * c + 2] = ry;
        }
    }
}

// ---------------------------------------------------------------------------
// Pass 2: correlation. CTA per (r, b, c-half). 768 threads = 64c x 6jj x 2th.
// ---------------------------------------------------------------------------
#define PB_BYTES   (9 * 15 * 64 * 8)          // 69120
#define A1F_BYTES  (5 * 16 * 64 * 4)          // 20480
#define A1F_OFF    PB_BYTES
#define STAGE_OFF  (PB_BYTES + A1F_BYTES)     // 89600
#define STAGE_ROW  3848                       // floats (3840 + 8 pad)
#define SMEM_BYTES (STAGE_OFF + 6 * STAGE_ROW * 4)   // 181952

__global__ __launch_bounds__(768, 1) void nc_corr_kernel(
    const float* __restrict__ in1, const float* __restrict__ in2,
    float* __restrict__ out)
{
    extern __shared__ char smraw[];
    u64*   PB    = (u64*)smraw;                       // [9][15][64]
    float* A1F   = (float*)(smraw + A1F_OFF);         // [5][16][64]
    float* stage = (float*)(smraw + STAGE_OFF);       // [6][STAGE_ROW]

    const int r   = blockIdx.x;
    const int b   = blockIdx.y;
    const int chv = blockIdx.z;        // c-half: 0 or 1
    const int tid = threadIdx.x;
    const int c   = tid & 63;          // channel within half
    const int hi  = tid >> 6;          // 0..11
    const int jj  = hi % 6;
    const int th  = hi / 6;            // t-half: 0 or 1
    const int ch  = chv * 64 + c;      // global channel

    // PB[row][x][c] = (A2[padcol x], A2[padcol x+1]) for pad2 row r+row.
    for (int i = tid; i < 9 * 15 * 64; i += 768) {
        int cc = i & 63, x = (i >> 6) % 15, row = i / (15 * 64);
        int irow = r + row - 4;
        float vlo = 0.f, vhi = 0.f;
        if ((unsigned)irow < 37u) {
            const float* base = in2 + ((b * 37 + irow) * 12) * 128 + chv * 64 + cc;
            int collo = x - 2, colhi = x - 1;
            if ((unsigned)collo < 12u) vlo = base[collo * 128];
            if ((unsigned)colhi < 12u) vhi = base[colhi * 128];
        }
        PB[i] = pk2(vlo, vhi);
    }
    // A1F[dr][col][c] = scalar f32 image1 value, pad1 row r+dr, pad col.
    for (int i = tid; i < 5 * 16 * 64; i += 768) {
        int cc = i & 63, col = (i >> 6) & 15, dr = i >> 10;
        int irow = r + dr - 2, icol = col - 2;
        float v = 0.f;
        if ((unsigned)irow < 37u && (unsigned)icol < 12u)
            v = in1[((b * 37 + irow) * 12 + icol) * 128 + chv * 64 + cc];
        A1F[i] = v;
    }
    __syncthreads();

    const u64* mBv = (const u64*)g_mBt;
    const u64* rBv = (const u64*)g_rBt;

    #pragma unroll 1
    for (int ph = 0; ph < 2; ph++) {
        const int j = jj + 6 * ph;

        float a1f[5][5];
        u64 acc[5][3];
        #pragma unroll
        for (int d = 0; d < 5; d++)
            #pragma unroll
            for (int tt = 0; tt < 3; tt++) acc[d][tt] = 0ull;

        // Fully static rho loop: dr = rho - d compile-time; a1f rows loaded
        // lazily (row dr first needed at rho == dr) to keep live ranges short.
        #pragma unroll
        for (int rho = 0; rho < 9; rho++) {
            if (rho < 5) {
                #pragma unroll
                for (int dc = 0; dc < 5; dc++)
                    a1f[rho][dc] = A1F[(rho * 16 + j + dc) * 64 + c];
            }
            u64 pb[9];
            #pragma unroll
            for (int k = 0; k < 9; k++)
                pb[k] = PB[(rho * 15 + 6 * th + k) * 64 + c];

            #pragma unroll
            for (int d = 0; d < 5; d++) {
                const int dr = rho - d;                 // compile-time
                if (dr >= 0 && dr < 5) {
                    #pragma unroll
                    for (int dc = 0; dc < 5; dc++) {
                        const u64 a = pk2(a1f[dr][dc], a1f[dr][dc]);
                        #pragma unroll
                        for (int tt = 0; tt < 3; tt++)
                            acc[d][tt] = fma2_(a, pb[2 * tt + dc], acc[d][tt]);
                    }
                }
            }
        }

        // Epilogue. row2 duplication: for d>=3, if r+d>38 the result equals
        // the d-2 result (patch2 row-start clamps) -> predicated selects.
        const int giA = ((b * 37 + r) * 12 + j) * 128 + ch;
        const float na = g_nA[giA];    // -25*mean1
        const float ra = g_rA[giA];
        const u64 na2 = pk2(na, na);
        const u64 ra2 = pk2(ra, ra);
        float* srow = stage + jj * STAGE_ROW + c * 60 + 6 * th;

        #pragma unroll
        for (int d = 0; d < 5; d++) {
            bool clamp = false;
            int  rowB  = r + d;
            if (d >= 3) { clamp = (r + d > 38); if (clamp) rowB = r + d - 2; }
            const int gbase = ((b * 39 + rowB) * 6 + 3 * th) * 128 + ch;
            #pragma unroll
            for (int tt = 0; tt < 3; tt++) {
                u64 s = acc[d][tt];
                if (d >= 3) s = clamp ? acc[d - 2][tt] : s;   // const indices
                u64 mbp = mBv[gbase + tt * 128];
                u64 rbp = rBv[gbase + tt * 128];
                u64 res = mul2_(fma2_(na2, mbp, s), mul2_(ra2, rbp));
                *(u64*)(srow + 12 * d + 2 * tt) = res;
            }
        }
        __syncthreads();

        // Coalesced flush: 6 j-tiles x 3840 contiguous floats (960 float4;
        // 960 % 32 == 0 so warps never straddle a tile).
        for (int f = tid; f < 5760; f += 768) {
            int jl = f / 960;
            int e  = (f - jl * 960) * 4;
            float4 v = *(float4*)(stage + jl * STAGE_ROW + e);
            *(float4*)(out + ((b * 37 + r) * 12 + jl + 6 * ph) * 7680
                           + chv * 3840 + e) = v;
        }
        __syncthreads();
    }
}

// ---------------------------------------------------------------------------
extern "C" void kernel_launch(void* const* d_in, const int* in_sizes, int n_in,
                              void* d_out, int out_size)
{
    const float* in1 = (const float*)d_in[0];
    const float* in2 = (const float*)d_in[1];
    float* out = (float*)d_out;

    cudaFuncSetAttribute(nc_corr_kernel,
                         cudaFuncAttributeMaxDynamicSharedMemorySize, SMEM_BYTES);

    nc_stats_kernel<<<dim3(NR + 39, NB), 384>>>(in1, in2);
    nc_corr_kernel<<<dim3(NR, NB, 2), 768, SMEM_BYTES>>>(in1, in2, out);
}